// round 1
// baseline (speedup 1.0000x reference)
#include <cuda_runtime.h>

#define BB 2
#define CC 64
#define HH 192
#define WW 192
#define HWX (HH*WW)
#define KK 7

// scratch: q and k in channel-major layout [b][c][h][w]
__device__ float d_qT[BB*CC*HWX];
__device__ float d_kT[BB*CC*HWX];

// ---------------------------------------------------------------------------
// Kernel 1: per-pixel LayerNorm over C, then matvec with conv_w [128 x 65]
// (z = [gn, cd]); k gets masked. Writes q,k channel-major.
// Block: 256 threads handle 32 consecutive pixels (one row segment).
// ---------------------------------------------------------------------------
#define K1_PIX 32
#define K1_NT 256

__global__ void __launch_bounds__(K1_NT)
mspn_k1(const float* __restrict__ g, const float* __restrict__ cd,
        const float* __restrict__ mask, const float* __restrict__ lnw,
        const float* __restrict__ lnb, const float* __restrict__ convw,
        const float* __restrict__ convb)
{
    __shared__ float zsh[65][K1_PIX];     // gn then z, in place
    __shared__ float wsh[128*65];         // conv_w
    __shared__ float mu_sh[K1_PIX], ri_sh[K1_PIX], mk_sh[K1_PIX];

    const int t = threadIdx.x;
    const int p0 = blockIdx.x * K1_PIX;       // linear pixel base (tiles never cross b or rows)
    const int b = p0 / HWX;
    const int hw0 = p0 - b*HWX;

    for (int i = t; i < 128*65; i += K1_NT) wsh[i] = convw[i];
    for (int i = t; i < 64*K1_PIX; i += K1_NT) {
        int c = i >> 5, px = i & 31;
        zsh[c][px] = g[(b*CC + c)*HWX + hw0 + px];
    }
    if (t < K1_PIX) { zsh[64][t] = cd[p0 + t]; mk_sh[t] = mask[p0 + t]; }
    __syncthreads();

    if (t < K1_PIX) {
        float s = 0.f;
        #pragma unroll
        for (int c = 0; c < 64; c++) s += zsh[c][t];
        float mu = s * (1.f/64.f);
        float v = 0.f;
        #pragma unroll
        for (int c = 0; c < 64; c++) { float d = zsh[c][t] - mu; v += d*d; }
        v *= (1.f/64.f);
        mu_sh[t] = mu;
        ri_sh[t] = rsqrtf(v + 1e-6f);
    }
    __syncthreads();

    for (int i = t; i < 64*K1_PIX; i += K1_NT) {
        int c = i >> 5, px = i & 31;
        zsh[c][px] = (zsh[c][px] - mu_sh[px]) * ri_sh[px] * lnw[c] + lnb[c];
    }
    __syncthreads();

    // matvec: lane = pixel (coalesced writes), warp id selects 8 output channels
    const int px = t & 31;
    const int wg = t >> 5;
    const int obase = (b*CC)*HWX + hw0 + px;
    for (int j = 0; j < 8; j++) {
        const int oc = wg*8 + j;
        const float* wq = &wsh[oc*65];
        const float* wk = &wsh[(oc+64)*65];
        float aq = 0.f, ak = 0.f;
        #pragma unroll
        for (int c = 0; c < 65; c++) {
            float z = zsh[c][px];        // bank = lane, conflict-free
            aq += z * wq[c];             // broadcast
            ak += z * wk[c];             // broadcast
        }
        aq += convb[oc];
        ak = (ak + convb[oc+64]) * mk_sh[px];
        d_qT[obase + oc*HWX] = aq;       // coalesced (lanes = consecutive pixels)
        d_kT[obase + oc*HWX] = ak;
    }
}

// ---------------------------------------------------------------------------
// Kernel 2: 7x7 clamped-window attention + rpb bias + softmax + cd/mask gather.
// Tile: 8 rows x 32 cols of output pixels, one thread per pixel, 49 logits in regs.
// k halo tile staged in SMEM in channel chunks of 8.
// ---------------------------------------------------------------------------
#define TX 32
#define TY 8
#define K2_NT 256
#define HR 14          // TY + 6 halo rows
#define HC 38          // TX + 6 halo cols
#define CHK 8

__global__ void __launch_bounds__(K2_NT)
mspn_k2(const float* __restrict__ cd, const float* __restrict__ sd,
        const float* __restrict__ mask, const float* __restrict__ rpb,
        float* __restrict__ out)
{
    __shared__ float ksh[CHK][HR*HC];
    __shared__ float qsh[CHK][TY*TX];
    __shared__ float cdsh[HR*HC];
    __shared__ float msh[HR*HC];
    __shared__ float rpbsh[169];

    const int t = threadIdx.x;
    const int b  = blockIdx.z;
    const int h0 = blockIdx.y * TY;
    const int w0 = blockIdx.x * TX;
    const int r_off = h0 - 3, c_off = w0 - 3;

    for (int i = t; i < HR*HC; i += K2_NT) {
        int rr = i / HC, cc = i - rr*HC;
        int r = r_off + rr, col = c_off + cc;
        float cv = 0.f, mv = 0.f;
        if (r >= 0 && r < HH && col >= 0 && col < WW) {
            int idx = b*HWX + r*WW + col;
            cv = cd[idx]; mv = mask[idx];
        }
        cdsh[i] = cv; msh[i] = mv;
    }
    if (t < 169) rpbsh[t] = rpb[t];

    const int lw = t & 31, lh = t >> 5;
    const int h = h0 + lh, w = w0 + lw;
    int rs = h - 3; if (rs < 0) rs = 0; if (rs > HH-KK) rs = HH-KK;
    int cs = w - 3; if (cs < 0) cs = 0; if (cs > WW-KK) cs = WW-KK;
    const int ri0 = rs - r_off;          // 0..7, same across warp
    const int ci0 = cs - c_off;          // consecutive across lanes (conflict-free)

    float attn[49];
    #pragma unroll
    for (int i = 0; i < 49; i++) attn[i] = 0.f;

    for (int cb = 0; cb < CC; cb += CHK) {
        __syncthreads();   // also orders cdsh/rpbsh writes before post-loop reads
        for (int i = t; i < CHK*HR*HC; i += K2_NT) {
            int c = i / (HR*HC);
            int rem = i - c*(HR*HC);
            int rr = rem / HC, cc = rem - rr*HC;
            int r = r_off + rr, col = c_off + cc;
            float v = 0.f;
            if (r >= 0 && r < HH && col >= 0 && col < WW)
                v = d_kT[(b*CC + cb + c)*HWX + r*WW + col];   // coalesced rows
            ksh[c][rem] = v;
        }
        for (int i = t; i < CHK*TY*TX; i += K2_NT) {
            int c = i >> 8, px = i & 255;
            qsh[c][px] = d_qT[(b*CC + cb + c)*HWX + (h0 + (px>>5))*WW + w0 + (px&31)];
        }
        __syncthreads();

        #pragma unroll
        for (int c = 0; c < CHK; c++) {
            float qc = qsh[c][t];
            #pragma unroll
            for (int i = 0; i < KK; i++) {
                const float* kr = &ksh[c][(ri0+i)*HC + ci0];
                #pragma unroll
                for (int j = 0; j < KK; j++)
                    attn[i*KK+j] += qc * kr[j];
            }
        }
    }

    // relative position bias + softmax
    const int pbr = 6 - (h - rs);
    const int pbc = 6 - (w - cs);
    float mx = -1e30f;
    #pragma unroll
    for (int i = 0; i < KK; i++) {
        #pragma unroll
        for (int j = 0; j < KK; j++) {
            float a = attn[i*KK+j] + rpbsh[(pbr+i)*13 + pbc + j];
            attn[i*KK+j] = a;
            mx = fmaxf(mx, a);
        }
    }
    float ssum = 0.f;
    #pragma unroll
    for (int i = 0; i < 49; i++) {
        float e = __expf(attn[i] - mx);
        attn[i] = e;
        ssum += e;
    }
    const float inv = 1.f / ssum;

    float cdo = 0.f, mo = 0.f;
    #pragma unroll
    for (int i = 0; i < KK; i++) {
        #pragma unroll
        for (int j = 0; j < KK; j++) {
            float a = attn[i*KK+j];
            cdo += a * cdsh[(ri0+i)*HC + ci0 + j];
            mo  += a * msh[(ri0+i)*HC + ci0 + j];
        }
    }
    cdo *= inv; mo *= inv;

    const int p = b*HWX + h*WW + w;
    const float m = mask[p], cdv = cd[p], sdv = sd[p];
    cdo = cdo*m + cdv*(1.f - m);
    if (sdv > 0.f) { cdo = sdv; mo = m; }
    out[p] = cdo;
    out[BB*HWX + p] = mo;
}

// ---------------------------------------------------------------------------
extern "C" void kernel_launch(void* const* d_in, const int* in_sizes, int n_in,
                              void* d_out, int out_size)
{
    const float* g     = (const float*)d_in[0];
    const float* cd    = (const float*)d_in[1];
    const float* sd    = (const float*)d_in[2];
    const float* mask  = (const float*)d_in[3];
    const float* lnw   = (const float*)d_in[4];
    const float* lnb   = (const float*)d_in[5];
    const float* convw = (const float*)d_in[6];
    const float* convb = (const float*)d_in[7];
    const float* rpb   = (const float*)d_in[8];
    float* out = (float*)d_out;

    mspn_k1<<<(BB*HWX)/K1_PIX, K1_NT>>>(g, cd, mask, lnw, lnb, convw, convb);

    dim3 grid2(WW/TX, HH/TY, BB);
    mspn_k2<<<grid2, K2_NT>>>(cd, sd, mask, rpb, out);
}

// round 2
// speedup vs baseline: 2.6438x; 2.6438x over previous
#include <cuda_runtime.h>

#define BB 2
#define CC 64
#define HH 192
#define WW 192
#define HWX (HH*WW)
#define KK 7

// q,k scratch in quad-channel layout: [b][c/4][hw] as float4 (channels c..c+3)
__device__ float4 d_q4[BB*16*HWX];
__device__ float4 d_k4[BB*16*HWX];

__device__ __forceinline__ void ffma2(unsigned long long &acc,
                                      unsigned long long a,
                                      unsigned long long b) {
    asm("fma.rn.f32x2 %0, %1, %2, %0;" : "+l"(acc) : "l"(a), "l"(b));
}
__device__ __forceinline__ float f2lo(unsigned long long v) {
    return __uint_as_float((unsigned)(v & 0xffffffffu));
}
__device__ __forceinline__ float f2hi(unsigned long long v) {
    return __uint_as_float((unsigned)(v >> 32));
}

// ---------------------------------------------------------------------------
// Kernel 1: LN + [128x65] matvec as register-blocked GEMM with f32x2 FMA.
// Block: 256 threads, 64 pixels, all 128 outputs.
//   z (65 x 64 px) duplicated into float2 (z,z) in smem
//   w (65 x 128)   transposed to wT[c][oc], stride 132
// Thread (lane, wid): pixels {lane, lane+32}, outputs oc0=wid*16 .. +15.
// Per k-step: 2 LDS.64 (dup z) + 4 LDS.128 (16 w, warp-uniform) + 16 FFMA2.
// ---------------------------------------------------------------------------
#define K1_PIX 64
#define K1_NT 256
#define WSTRIDE 132
#define K1_SMEM (65*K1_PIX*8 + 65*WSTRIDE*4)

__global__ void __launch_bounds__(K1_NT)
mspn_k1(const float* __restrict__ g, const float* __restrict__ cd,
        const float* __restrict__ mask, const float* __restrict__ lnw,
        const float* __restrict__ lnb, const float* __restrict__ convw,
        const float* __restrict__ convb)
{
    extern __shared__ __align__(16) char dsm[];
    float2* zsh = (float2*)dsm;                       // [65][64]
    float*  wsh = (float*)(dsm + 65*K1_PIX*8);        // [65][WSTRIDE]
    __shared__ float mu_sh[K1_PIX], ri_sh[K1_PIX], mk_sh[K1_PIX];

    const int t = threadIdx.x;
    const int p0 = blockIdx.x * K1_PIX;
    const int b = p0 / HWX;
    const int hw0 = p0 - b*HWX;

    // stage weights transposed: wT[c][oc]
    for (int i = t; i < 128*65; i += K1_NT) {
        int oc = i / 65, c = i - oc*65;
        wsh[c*WSTRIDE + oc] = convw[i];
    }
    // stage g (x-half only for now)
    for (int i = t; i < 64*K1_PIX; i += K1_NT) {
        int c = i >> 6, px = i & 63;
        zsh[c*K1_PIX + px].x = g[(b*CC + c)*HWX + hw0 + px];
    }
    if (t < K1_PIX) {
        float cv = cd[p0 + t];
        zsh[64*K1_PIX + t] = make_float2(cv, cv);
        mk_sh[t] = mask[p0 + t];
    }
    __syncthreads();

    if (t < K1_PIX) {
        float s = 0.f;
        #pragma unroll
        for (int c = 0; c < 64; c++) s += zsh[c*K1_PIX + t].x;
        float mu = s * (1.f/64.f);
        float v = 0.f;
        #pragma unroll
        for (int c = 0; c < 64; c++) { float d = zsh[c*K1_PIX + t].x - mu; v += d*d; }
        mu_sh[t] = mu;
        ri_sh[t] = rsqrtf(v * (1.f/64.f) + 1e-6f);
    }
    __syncthreads();

    for (int i = t; i < 64*K1_PIX; i += K1_NT) {
        int c = i >> 6, px = i & 63;
        float v = (zsh[c*K1_PIX + px].x - mu_sh[px]) * ri_sh[px] * lnw[c] + lnb[c];
        zsh[c*K1_PIX + px] = make_float2(v, v);
    }
    __syncthreads();

    // GEMM
    const int lane = t & 31, wid = t >> 5;
    const int oc0 = wid * 16;

    unsigned long long acc[16];
    #pragma unroll
    for (int i = 0; i < 16; i++) acc[i] = 0ULL;

    #pragma unroll 13
    for (int c = 0; c < 65; c++) {
        unsigned long long z0 = *(const unsigned long long*)&zsh[c*K1_PIX + lane];
        unsigned long long z1 = *(const unsigned long long*)&zsh[c*K1_PIX + lane + 32];
        const float* wr = &wsh[c*WSTRIDE + oc0];
        ulonglong2 wa = *(const ulonglong2*)(wr);
        ulonglong2 wb = *(const ulonglong2*)(wr + 4);
        ulonglong2 wc = *(const ulonglong2*)(wr + 8);
        ulonglong2 wd = *(const ulonglong2*)(wr + 12);
        ffma2(acc[0], z0, wa.x); ffma2(acc[1], z0, wa.y);
        ffma2(acc[2], z0, wb.x); ffma2(acc[3], z0, wb.y);
        ffma2(acc[4], z0, wc.x); ffma2(acc[5], z0, wc.y);
        ffma2(acc[6], z0, wd.x); ffma2(acc[7], z0, wd.y);
        ffma2(acc[8],  z1, wa.x); ffma2(acc[9],  z1, wa.y);
        ffma2(acc[10], z1, wb.x); ffma2(acc[11], z1, wb.y);
        ffma2(acc[12], z1, wc.x); ffma2(acc[13], z1, wc.y);
        ffma2(acc[14], z1, wd.x); ffma2(acc[15], z1, wd.y);
    }

    // epilogue: bias (+mask for k half), write quad-channel float4
    const bool isk = (oc0 >= 64);
    const int cq0 = (isk ? oc0 - 64 : oc0) >> 2;      // quad base (0..15)
    float4* dst = isk ? d_k4 : d_q4;
    float bias[16];
    #pragma unroll
    for (int i = 0; i < 16; i++) bias[i] = convb[oc0 + i];

    #pragma unroll
    for (int px = 0; px < 2; px++) {
        const int pl = lane + px*32;
        const int pix = hw0 + pl;
        const float m = mk_sh[pl];
        float vals[16];
        #pragma unroll
        for (int j = 0; j < 8; j++) {
            unsigned long long a = acc[px*8 + j];
            vals[2*j]   = f2lo(a) + bias[2*j];
            vals[2*j+1] = f2hi(a) + bias[2*j+1];
        }
        if (isk) {
            #pragma unroll
            for (int i = 0; i < 16; i++) vals[i] *= m;
        }
        #pragma unroll
        for (int q = 0; q < 4; q++) {
            float4 o = make_float4(vals[4*q], vals[4*q+1], vals[4*q+2], vals[4*q+3]);
            dst[(b*16 + cq0 + q)*HWX + pix] = o;
        }
    }
}

// ---------------------------------------------------------------------------
// Kernel 2: 7x7 clamped-window attention, float4 (4-channel) vectorized.
// ---------------------------------------------------------------------------
#define TX 32
#define TY 8
#define K2_NT 256
#define HR 14
#define HC 38

__global__ void __launch_bounds__(K2_NT)
mspn_k2(const float* __restrict__ cd, const float* __restrict__ sd,
        const float* __restrict__ mask, const float* __restrict__ rpb,
        float* __restrict__ out)
{
    __shared__ float4 ksh[2][HR*HC];
    __shared__ float4 qsh[2][TY*TX];
    __shared__ float cdsh[HR*HC];
    __shared__ float msh[HR*HC];
    __shared__ float rpbsh[169];

    const int t = threadIdx.x;
    const int b  = blockIdx.z;
    const int h0 = blockIdx.y * TY;
    const int w0 = blockIdx.x * TX;
    const int r_off = h0 - 3, c_off = w0 - 3;

    for (int i = t; i < HR*HC; i += K2_NT) {
        int rr = i / HC, cc = i - rr*HC;
        int r = r_off + rr, col = c_off + cc;
        float cv = 0.f, mv = 0.f;
        if (r >= 0 && r < HH && col >= 0 && col < WW) {
            int idx = b*HWX + r*WW + col;
            cv = cd[idx]; mv = mask[idx];
        }
        cdsh[i] = cv; msh[i] = mv;
    }
    if (t < 169) rpbsh[t] = rpb[t];

    const int lw = t & 31, lh = t >> 5;
    const int h = h0 + lh, w = w0 + lw;
    int rs = h - 3; if (rs < 0) rs = 0; if (rs > HH-KK) rs = HH-KK;
    int cs = w - 3; if (cs < 0) cs = 0; if (cs > WW-KK) cs = WW-KK;
    const int ri0 = rs - r_off;
    const int ci0 = cs - c_off;

    float attn[49];
    #pragma unroll
    for (int i = 0; i < 49; i++) attn[i] = 0.f;

    const int qpix = (h0 + lh)*WW + w0 + lw;

    for (int cq = 0; cq < 16; cq += 2) {
        __syncthreads();   // also orders cdsh/rpbsh before post-loop reads
        #pragma unroll
        for (int j = 0; j < 2; j++) {
            const float4* src = &d_k4[(b*16 + cq + j)*HWX];
            for (int i = t; i < HR*HC; i += K2_NT) {
                int rr = i / HC, cc = i - rr*HC;
                int r = r_off + rr, col = c_off + cc;
                float4 v = make_float4(0.f, 0.f, 0.f, 0.f);
                if (r >= 0 && r < HH && col >= 0 && col < WW)
                    v = src[r*WW + col];
                ksh[j][i] = v;
            }
            qsh[j][t] = d_q4[(b*16 + cq + j)*HWX + qpix];
        }
        __syncthreads();

        #pragma unroll
        for (int j = 0; j < 2; j++) {
            float4 q4 = qsh[j][t];
            #pragma unroll
            for (int i = 0; i < KK; i++) {
                const float4* kr = &ksh[j][(ri0+i)*HC + ci0];
                #pragma unroll
                for (int jj = 0; jj < KK; jj++) {
                    float4 k4 = kr[jj];
                    attn[i*KK+jj] += q4.x*k4.x + q4.y*k4.y + q4.z*k4.z + q4.w*k4.w;
                }
            }
        }
    }

    // bias + softmax
    const int pbr = 6 - (h - rs);
    const int pbc = 6 - (w - cs);
    float mx = -1e30f;
    #pragma unroll
    for (int i = 0; i < KK; i++) {
        #pragma unroll
        for (int j = 0; j < KK; j++) {
            float a = attn[i*KK+j] + rpbsh[(pbr+i)*13 + pbc + j];
            attn[i*KK+j] = a;
            mx = fmaxf(mx, a);
        }
    }
    float ssum = 0.f;
    #pragma unroll
    for (int i = 0; i < 49; i++) {
        float e = __expf(attn[i] - mx);
        attn[i] = e;
        ssum += e;
    }
    const float inv = 1.f / ssum;

    float cdo = 0.f, mo = 0.f;
    #pragma unroll
    for (int i = 0; i < KK; i++) {
        #pragma unroll
        for (int j = 0; j < KK; j++) {
            float a = attn[i*KK+j];
            cdo += a * cdsh[(ri0+i)*HC + ci0 + j];
            mo  += a * msh[(ri0+i)*HC + ci0 + j];
        }
    }
    cdo *= inv; mo *= inv;

    const int p = b*HWX + h*WW + w;
    const float m = mask[p], cdv = cd[p], sdv = sd[p];
    cdo = cdo*m + cdv*(1.f - m);
    if (sdv > 0.f) { cdo = sdv; mo = m; }
    out[p] = cdo;
    out[BB*HWX + p] = mo;
}

// ---------------------------------------------------------------------------
extern "C" void kernel_launch(void* const* d_in, const int* in_sizes, int n_in,
                              void* d_out, int out_size)
{
    const float* g     = (const float*)d_in[0];
    const float* cd    = (const float*)d_in[1];
    const float* sd    = (const float*)d_in[2];
    const float* mask  = (const float*)d_in[3];
    const float* lnw   = (const float*)d_in[4];
    const float* lnb   = (const float*)d_in[5];
    const float* convw = (const float*)d_in[6];
    const float* convb = (const float*)d_in[7];
    const float* rpb   = (const float*)d_in[8];
    float* out = (float*)d_out;

    cudaFuncSetAttribute(mspn_k1, cudaFuncAttributeMaxDynamicSharedMemorySize, K1_SMEM);
    mspn_k1<<<(BB*HWX)/K1_PIX, K1_NT, K1_SMEM>>>(g, cd, mask, lnw, lnb, convw, convb);

    dim3 grid2(WW/TX, HH/TY, BB);
    mspn_k2<<<grid2, K2_NT>>>(cd, sd, mask, rpb, out);
}

// round 4
// speedup vs baseline: 2.7814x; 1.0520x over previous
#include <cuda_runtime.h>

#define BB 2
#define CC 64
#define HH 192
#define WW 192
#define HWX (HH*WW)
#define KK 7

// q,k scratch in quad-channel layout: [b][c/4][hw] as float4 (channels c..c+3)
__device__ float4 d_q4[BB*16*HWX];
__device__ float4 d_k4[BB*16*HWX];

__device__ __forceinline__ void ffma2(unsigned long long &acc,
                                      unsigned long long a,
                                      unsigned long long b) {
    asm("fma.rn.f32x2 %0, %1, %2, %0;" : "+l"(acc) : "l"(a), "l"(b));
}
__device__ __forceinline__ float f2lo(unsigned long long v) {
    return __uint_as_float((unsigned)(v & 0xffffffffu));
}
__device__ __forceinline__ float f2hi(unsigned long long v) {
    return __uint_as_float((unsigned)(v >> 32));
}

// ---------------------------------------------------------------------------
// Kernel 1: LN + [128x65] matvec, register-blocked, f32x2 FMA.
// ---------------------------------------------------------------------------
#define K1_PIX 64
#define K1_NT 256
#define WSTRIDE 132
#define K1_SMEM (65*K1_PIX*8 + 65*WSTRIDE*4)

__global__ void __launch_bounds__(K1_NT)
mspn_k1(const float* __restrict__ g, const float* __restrict__ cd,
        const float* __restrict__ mask, const float* __restrict__ lnw,
        const float* __restrict__ lnb, const float* __restrict__ convw,
        const float* __restrict__ convb)
{
    extern __shared__ __align__(16) char dsm[];
    float2* zsh = (float2*)dsm;                       // [65][64]
    float*  wsh = (float*)(dsm + 65*K1_PIX*8);        // [65][WSTRIDE]
    __shared__ float mu_sh[K1_PIX], ri_sh[K1_PIX], mk_sh[K1_PIX];
    __shared__ float bsh[128];

    const int t = threadIdx.x;
    const int p0 = blockIdx.x * K1_PIX;
    const int b = p0 / HWX;
    const int hw0 = p0 - b*HWX;

    for (int i = t; i < 128*65; i += K1_NT) {
        int oc = i / 65, c = i - oc*65;
        wsh[c*WSTRIDE + oc] = convw[i];
    }
    for (int i = t; i < 64*K1_PIX; i += K1_NT) {
        int c = i >> 6, px = i & 63;
        zsh[c*K1_PIX + px].x = g[(b*CC + c)*HWX + hw0 + px];
    }
    if (t < K1_PIX) {
        float cv = cd[p0 + t];
        zsh[64*K1_PIX + t] = make_float2(cv, cv);
        mk_sh[t] = mask[p0 + t];
    }
    if (t >= 128 && t < 256) bsh[t-128] = convb[t-128];
    __syncthreads();

    if (t < K1_PIX) {
        float s = 0.f;
        #pragma unroll
        for (int c = 0; c < 64; c++) s += zsh[c*K1_PIX + t].x;
        float mu = s * (1.f/64.f);
        float v = 0.f;
        #pragma unroll
        for (int c = 0; c < 64; c++) { float d = zsh[c*K1_PIX + t].x - mu; v += d*d; }
        mu_sh[t] = mu;
        ri_sh[t] = rsqrtf(v * (1.f/64.f) + 1e-6f);
    }
    __syncthreads();

    for (int i = t; i < 64*K1_PIX; i += K1_NT) {
        int c = i >> 6, px = i & 63;
        float v = (zsh[c*K1_PIX + px].x - mu_sh[px]) * ri_sh[px] * lnw[c] + lnb[c];
        zsh[c*K1_PIX + px] = make_float2(v, v);
    }
    __syncthreads();

    const int lane = t & 31, wid = t >> 5;
    const int oc0 = wid * 16;

    unsigned long long acc[16];
    #pragma unroll
    for (int i = 0; i < 16; i++) acc[i] = 0ULL;

    #pragma unroll 13
    for (int c = 0; c < 65; c++) {
        unsigned long long z0 = *(const unsigned long long*)&zsh[c*K1_PIX + lane];
        unsigned long long z1 = *(const unsigned long long*)&zsh[c*K1_PIX + lane + 32];
        const float* wr = &wsh[c*WSTRIDE + oc0];
        ulonglong2 wa = *(const ulonglong2*)(wr);
        ulonglong2 wb = *(const ulonglong2*)(wr + 4);
        ulonglong2 wc = *(const ulonglong2*)(wr + 8);
        ulonglong2 wd = *(const ulonglong2*)(wr + 12);
        ffma2(acc[0], z0, wa.x); ffma2(acc[1], z0, wa.y);
        ffma2(acc[2], z0, wb.x); ffma2(acc[3], z0, wb.y);
        ffma2(acc[4], z0, wc.x); ffma2(acc[5], z0, wc.y);
        ffma2(acc[6], z0, wd.x); ffma2(acc[7], z0, wd.y);
        ffma2(acc[8],  z1, wa.x); ffma2(acc[9],  z1, wa.y);
        ffma2(acc[10], z1, wb.x); ffma2(acc[11], z1, wb.y);
        ffma2(acc[12], z1, wc.x); ffma2(acc[13], z1, wc.y);
        ffma2(acc[14], z1, wd.x); ffma2(acc[15], z1, wd.y);
    }

    const bool isk = (oc0 >= 64);
    const int cq0 = (isk ? oc0 - 64 : oc0) >> 2;
    float4* dst = isk ? d_k4 : d_q4;
    float bias[16];
    #pragma unroll
    for (int i = 0; i < 16; i++) bias[i] = bsh[oc0 + i];

    #pragma unroll
    for (int px = 0; px < 2; px++) {
        const int pl = lane + px*32;
        const int pix = hw0 + pl;
        const float m = mk_sh[pl];
        float vals[16];
        #pragma unroll
        for (int j = 0; j < 8; j++) {
            unsigned long long a = acc[px*8 + j];
            vals[2*j]   = f2lo(a) + bias[2*j];
            vals[2*j+1] = f2hi(a) + bias[2*j+1];
        }
        if (isk) {
            #pragma unroll
            for (int i = 0; i < 16; i++) vals[i] *= m;
        }
        #pragma unroll
        for (int q = 0; q < 4; q++) {
            float4 o = make_float4(vals[4*q], vals[4*q+1], vals[4*q+2], vals[4*q+3]);
            dst[(b*16 + cq0 + q)*HWX + pix] = o;
        }
    }
}

// ---------------------------------------------------------------------------
// Kernel 2: 7x7 clamped-window attention. Vertical pixel-pair per thread:
// thread handles rows (2*lh, 2*lh+1), sharing an 8-row x 7-tap union of k
// loads for both pixels' 98 logits. Double-buffered k staging, q via LDG.
// ---------------------------------------------------------------------------
#define TX 32
#define TYO 16
#define K2_NT 256
#define HR 22          // TYO + 6
#define HC 38          // TX + 6

__global__ void __launch_bounds__(K2_NT)
mspn_k2(const float* __restrict__ cd, const float* __restrict__ sd,
        const float* __restrict__ mask, const float* __restrict__ rpb,
        float* __restrict__ out)
{
    __shared__ float4 ksh[2][HR*HC];
    __shared__ float cdsh[HR*HC];
    __shared__ float msh[HR*HC];
    __shared__ float rpbsh[169];

    const int t = threadIdx.x;
    const int b  = blockIdx.z;
    const int h0 = blockIdx.y * TYO;
    const int w0 = blockIdx.x * TX;
    const int r_off = h0 - 3, c_off = w0 - 3;

    // prologue: cd/mask halo + rpb
    for (int i = t; i < HR*HC; i += K2_NT) {
        int rr = i / HC, cc = i - rr*HC;
        int r = r_off + rr, col = c_off + cc;
        float cv = 0.f, mv = 0.f;
        if (r >= 0 && r < HH && col >= 0 && col < WW) {
            int idx = b*HWX + r*WW + col;
            cv = cd[idx]; mv = mask[idx];
        }
        cdsh[i] = cv; msh[i] = mv;
    }
    if (t < 169) rpbsh[t] = rpb[t];

    const int lane = t & 31, lh = t >> 5;
    const int h0g = h0 + 2*lh, h1g = h0g + 1;
    const int w = w0 + lane;
    int rs0 = h0g - 3; if (rs0 < 0) rs0 = 0; if (rs0 > HH-KK) rs0 = HH-KK;
    int rs1 = h1g - 3; if (rs1 < 0) rs1 = 0; if (rs1 > HH-KK) rs1 = HH-KK;
    int cs  = w   - 3; if (cs  < 0) cs  = 0; if (cs  > WW-KK) cs  = WW-KK;
    const int d   = rs1 - rs0;           // 0 or 1, warp-uniform
    const int ri0 = rs0 - r_off;         // union row base in smem
    const int ci0 = cs  - c_off;

    float a0[49], a1[49];
    #pragma unroll
    for (int i = 0; i < 49; i++) { a0[i] = 0.f; a1[i] = 0.f; }

    const int qp0 = h0g*WW + w, qp1 = h1g*WW + w;

    // stage quad 0 into buffer 0
    {
        const float4* src = &d_k4[(b*16 + 0)*HWX];
        for (int i = t; i < HR*HC; i += K2_NT) {
            int rr = i / HC, cc = i - rr*HC;
            int r = r_off + rr, col = c_off + cc;
            float4 v = make_float4(0.f,0.f,0.f,0.f);
            if (r >= 0 && r < HH && col >= 0 && col < WW) v = src[r*WW + col];
            ksh[0][i] = v;
        }
    }

    for (int cq = 0; cq < 16; cq++) {
        __syncthreads();
        if (cq < 15) {                      // stage next quad into other buffer
            const float4* src = &d_k4[(b*16 + cq + 1)*HWX];
            const int buf = (cq + 1) & 1;
            for (int i = t; i < HR*HC; i += K2_NT) {
                int rr = i / HC, cc = i - rr*HC;
                int r = r_off + rr, col = c_off + cc;
                float4 v = make_float4(0.f,0.f,0.f,0.f);
                if (r >= 0 && r < HH && col >= 0 && col < WW) v = src[r*WW + col];
                ksh[buf][i] = v;
            }
        }
        const float4 q0 = d_q4[(b*16 + cq)*HWX + qp0];
        const float4 q1 = d_q4[(b*16 + cq)*HWX + qp1];
        const float4* kb = &ksh[cq & 1][ri0*HC + ci0];

        if (d == 1) {
            // union rows 0..7: row r -> a0 row r (r<7), a1 row r-1 (r>=1)
            {   // r = 0: a0 only
                #pragma unroll
                for (int j = 0; j < KK; j++) {
                    float4 k4 = kb[j];
                    a0[j] += q0.x*k4.x + q0.y*k4.y + q0.z*k4.z + q0.w*k4.w;
                }
            }
            #pragma unroll
            for (int r = 1; r < 7; r++) {
                #pragma unroll
                for (int j = 0; j < KK; j++) {
                    float4 k4 = kb[r*HC + j];
                    a0[r*KK+j]     += q0.x*k4.x + q0.y*k4.y + q0.z*k4.z + q0.w*k4.w;
                    a1[(r-1)*KK+j] += q1.x*k4.x + q1.y*k4.y + q1.z*k4.z + q1.w*k4.w;
                }
            }
            {   // r = 7: a1 only
                #pragma unroll
                for (int j = 0; j < KK; j++) {
                    float4 k4 = kb[7*HC + j];
                    a1[42+j] += q1.x*k4.x + q1.y*k4.y + q1.z*k4.z + q1.w*k4.w;
                }
            }
        } else {
            // same clamp: both pixels use rows 0..6
            #pragma unroll
            for (int r = 0; r < 7; r++) {
                #pragma unroll
                for (int j = 0; j < KK; j++) {
                    float4 k4 = kb[r*HC + j];
                    a0[r*KK+j] += q0.x*k4.x + q0.y*k4.y + q0.z*k4.z + q0.w*k4.w;
                    a1[r*KK+j] += q1.x*k4.x + q1.y*k4.y + q1.z*k4.z + q1.w*k4.w;
                }
            }
        }
    }

    const int pbc = 6 - (w - cs);

    // ---- pixel 0 ----
    {
        const int pbr = 6 - (h0g - rs0);
        float mx = -1e30f;
        #pragma unroll
        for (int i = 0; i < KK; i++)
            #pragma unroll
            for (int j = 0; j < KK; j++) {
                float a = a0[i*KK+j] + rpbsh[(pbr+i)*13 + pbc + j];
                a0[i*KK+j] = a;
                mx = fmaxf(mx, a);
            }
        float ssum = 0.f;
        #pragma unroll
        for (int i = 0; i < 49; i++) { float e = __expf(a0[i]-mx); a0[i]=e; ssum+=e; }
        const float inv = 1.f/ssum;
        float cdo = 0.f, mo = 0.f;
        #pragma unroll
        for (int i = 0; i < KK; i++) {
            const int base = (ri0+i)*HC + ci0;
            #pragma unroll
            for (int j = 0; j < KK; j++) {
                float a = a0[i*KK+j];
                cdo += a * cdsh[base+j];
                mo  += a * msh[base+j];
            }
        }
        cdo *= inv; mo *= inv;
        const int p = b*HWX + h0g*WW + w;
        const float m = mask[p], cdv = cd[p], sdv = sd[p];
        cdo = cdo*m + cdv*(1.f - m);
        if (sdv > 0.f) { cdo = sdv; mo = m; }
        out[p] = cdo;
        out[BB*HWX + p] = mo;
    }
    // ---- pixel 1 ----
    {
        const int ri1 = ri0 + d;
        const int pbr = 6 - (h1g - rs1);
        float mx = -1e30f;
        #pragma unroll
        for (int i = 0; i < KK; i++)
            #pragma unroll
            for (int j = 0; j < KK; j++) {
                float a = a1[i*KK+j] + rpbsh[(pbr+i)*13 + pbc + j];
                a1[i*KK+j] = a;
                mx = fmaxf(mx, a);
            }
        float ssum = 0.f;
        #pragma unroll
        for (int i = 0; i < 49; i++) { float e = __expf(a1[i]-mx); a1[i]=e; ssum+=e; }
        const float inv = 1.f/ssum;
        float cdo = 0.f, mo = 0.f;
        #pragma unroll
        for (int i = 0; i < KK; i++) {
            const int base = (ri1+i)*HC + ci0;
            #pragma unroll
            for (int j = 0; j < KK; j++) {
                float a = a1[i*KK+j];
                cdo += a * cdsh[base+j];
                mo  += a * msh[base+j];
            }
        }
        cdo *= inv; mo *= inv;
        const int p = b*HWX + h1g*WW + w;
        const float m = mask[p], cdv = cd[p], sdv = sd[p];
        cdo = cdo*m + cdv*(1.f - m);
        if (sdv > 0.f) { cdo = sdv; mo = m; }
        out[p] = cdo;
        out[BB*HWX + p] = mo;
    }
}

// ---------------------------------------------------------------------------
extern "C" void kernel_launch(void* const* d_in, const int* in_sizes, int n_in,
                              void* d_out, int out_size)
{
    const float* g     = (const float*)d_in[0];
    const float* cd    = (const float*)d_in[1];
    const float* sd    = (const float*)d_in[2];
    const float* mask  = (const float*)d_in[3];
    const float* lnw   = (const float*)d_in[4];
    const float* lnb   = (const float*)d_in[5];
    const float* convw = (const float*)d_in[6];
    const float* convb = (const float*)d_in[7];
    const float* rpb   = (const float*)d_in[8];
    float* out = (float*)d_out;

    cudaFuncSetAttribute(mspn_k1, cudaFuncAttributeMaxDynamicSharedMemorySize, K1_SMEM);
    mspn_k1<<<(BB*HWX)/K1_PIX, K1_NT, K1_SMEM>>>(g, cd, mask, lnw, lnb, convw, convb);

    dim3 grid2(WW/TX, HH/TYO, BB);
    mspn_k2<<<grid2, K2_NT>>>(cd, sd, mask, rpb, out);
}